// round 2
// baseline (speedup 1.0000x reference)
#include <cuda_runtime.h>
#include <cuda_fp16.h>

#define BSZ 32
#define TT 512
#define DD 128
#define MM 50
#define NUMC 4096
#define AWC (NUMC + DD)
#define G4 512
#define RR (BSZ * TT)

// ---------------- scratch (static device arrays; no allocation) ----------------
__device__ float g_k[RR * DD];
__device__ float g_yq[RR * DD];
__device__ float g_w[RR * MM];
__device__ unsigned long long g_pack[RR * 2];
__device__ int g_prev[RR];
__device__ int g_match[RR];
__device__ float g_f[RR * DD];
__device__ float g_gi[RR * G4];
__device__ float g_H[RR * DD];
__device__ float g_C[RR * DD];

__device__ __forceinline__ float warp_sum(float v) {
#pragma unroll
    for (int o = 16; o; o >>= 1) v += __shfl_xor_sync(0xffffffffu, v, o);
    return v;
}

// ---------------- Kernel A: gather + logits + softmax + quantize/pack ----------
__global__ __launch_bounds__(256) void kA(const int* __restrict__ q,
                                          const int* __restrict__ r,
                                          const float* __restrict__ k_emb,
                                          const float* __restrict__ Mk,
                                          const float* __restrict__ aW) {
    __shared__ float sMk[MM * DD];
    __shared__ float sk[DD];
    __shared__ float slog[MM];
    const int tid = threadIdx.x;
    for (int i = tid; i < MM * DD; i += 256) sMk[i] = Mk[i];
    const int base = blockIdx.x * 64;
    const int warp = tid >> 5, lane = tid & 31;

    for (int p = 0; p < 64; p++) {
        const int idx = base + p;
        __syncthreads();
        if (tid < DD) {
            const int qv = q[idx];
            const float kv = k_emb[qv * DD + tid];
            sk[tid] = kv;
            g_k[idx * DD + tid] = kv;
            g_yq[idx * DD + tid] = aW[tid * AWC + qv] * (float)r[idx];
        }
        __syncthreads();
        for (int m = warp; m < MM; m += 8) {
            float s = 0.f;
#pragma unroll
            for (int c = 0; c < 4; c++) s = fmaf(sk[c * 32 + lane], sMk[m * DD + c * 32 + lane], s);
            s = warp_sum(s);
            if (lane == 0) slog[m] = s;
        }
        __syncthreads();
        if (warp == 0) {
            float l0 = (lane < MM) ? slog[lane] : -1e30f;
            float l1 = (lane + 32 < MM) ? slog[lane + 32] : -1e30f;
            float mx = fmaxf(l0, l1);
#pragma unroll
            for (int o = 16; o; o >>= 1) mx = fmaxf(mx, __shfl_xor_sync(0xffffffffu, mx, o));
            float e0 = (lane < MM) ? expf(l0 - mx) : 0.f;
            float e1 = (lane + 32 < MM) ? expf(l1 - mx) : 0.f;
            float ssum = warp_sum(e0 + e1);
            float w0 = e0 / ssum, w1 = e1 / ssum;
            if (lane < MM) g_w[idx * MM + lane] = w0;
            if (lane + 32 < MM) g_w[idx * MM + lane + 32] = w1;
            // quantization codes (match python constant evaluation: double then cast)
            const float ta = 0.075f;
            const float dba = (float)(0.088 - 0.075);
            const float dcb = (float)(1.0 - 0.088);
            float tw0 = fmaxf(fminf((w0 - ta) / dba, (1.0f - w0) / dcb), 0.f);
            float tw1 = fmaxf(fminf((w1 - ta) / dba, (1.0f - w1) / dcb), 0.f);
            int c0 = (lane < MM) ? (tw0 >= 0.6f ? 2 : (tw0 >= 0.1f ? 1 : 0)) : 0;
            int c1 = (lane + 32 < MM) ? (tw1 >= 0.6f ? 2 : (tw1 >= 0.1f ? 1 : 0)) : 0;
            unsigned b00 = __ballot_sync(0xffffffffu, c0 & 1);
            unsigned b01 = __ballot_sync(0xffffffffu, c0 >> 1);
            unsigned b10 = __ballot_sync(0xffffffffu, c1 & 1);
            unsigned b11 = __ballot_sync(0xffffffffu, c1 >> 1);
            if (lane == 0) {
                g_pack[idx * 2 + 0] = (unsigned long long)b00 | ((unsigned long long)b01 << 32);
                g_pack[idx * 2 + 1] = (unsigned long long)b10 | ((unsigned long long)b11 << 32);
            }
        }
    }
}

// ---------------- Kernel B: matched/prev via warp ballot backward scan ---------
__global__ __launch_bounds__(256) void kB() {
    const int gw = blockIdx.x * 8 + (threadIdx.x >> 5);  // row = b*T + i
    const int lane = threadIdx.x & 31;
    const int b = gw / TT, i = gw % TT;
    const unsigned long long m0 = g_pack[gw * 2], m1 = g_pack[gw * 2 + 1];
    const unsigned long long* rp = &g_pack[(size_t)b * TT * 2];
    int prev = 0, matched = 0;
    for (int base = i - 1; base >= 0; base -= 32) {
        const int j = base - lane;
        const bool eq = (j >= 0) && (rp[j * 2] == m0) && (rp[j * 2 + 1] == m1);
        const unsigned msk = __ballot_sync(0xffffffffu, eq);
        if (msk) { matched = 1; prev = base - (__ffs(msk) - 1); break; }
    }
    if (lane == 0) { g_prev[gw] = prev; g_match[gw] = matched; }
}

// ---------------- Kernel C: sequential memory-network scan (1 block / batch) ---
// smem layout (bytes):
//   fT2   [128][128] half2 : 0       .. 65536
//   aT2   [ 64][128] half2 : 65536   .. 98304
//   eaT2  [ 64][256] half2 : 98304   .. 163840
//   Mv    [ 50][128] f32   : 163840  .. 189440
//   xbuf  [256] f32        : 189440  .. 190464
//   fbuf  [128] f32        : 190464  .. 190976
//   ybuf  [128] f32        : 190976  .. 191488
//   wbuf  [ 64] f32        : 191488  .. 191744
//   biases 4x128 f32       : 191744  .. 193792
#define C_SMEM 193792
__global__ __launch_bounds__(128) void kC(const float* __restrict__ fW,
                                          const float* __restrict__ fb,
                                          const float* __restrict__ aW,
                                          const float* __restrict__ ab,
                                          const float* __restrict__ eW,
                                          const float* __restrict__ eb,
                                          const float* __restrict__ addW,
                                          const float* __restrict__ addb,
                                          const float* __restrict__ Mv0) {
    extern __shared__ char sm[];
    half2* fT2 = (half2*)sm;
    half2* aT2 = (half2*)(sm + 65536);
    half2* eaT2 = (half2*)(sm + 98304);
    float* Mv = (float*)(sm + 163840);
    float* xbuf = (float*)(sm + 189440);
    float* fbuf = (float*)(sm + 190464);
    float* ybuf = (float*)(sm + 190976);
    float* wbuf = (float*)(sm + 191488);
    float* bfb = (float*)(sm + 191744);
    float* bab = bfb + 128;
    float* beb = bab + 128;
    float* badb = beb + 128;

    const int tid = threadIdx.x;
    const int b = blockIdx.x;

    // load + transpose weights into smem (half2 along input dim)
    for (int i = tid; i < 128 * 128; i += 128) {
        const int jp = i >> 7, o = i & 127;
        fT2[i] = __floats2half2_rn(fW[o * 256 + 2 * jp], fW[o * 256 + 2 * jp + 1]);
    }
    for (int i = tid; i < 64 * 128; i += 128) {
        const int jp = i >> 7, o = i & 127;
        aT2[i] = __floats2half2_rn(aW[o * AWC + NUMC + 2 * jp], aW[o * AWC + NUMC + 2 * jp + 1]);
        eaT2[jp * 256 + o] = __floats2half2_rn(eW[o * 128 + 2 * jp], eW[o * 128 + 2 * jp + 1]);
        eaT2[jp * 256 + 128 + o] =
            __floats2half2_rn(addW[o * 128 + 2 * jp], addW[o * 128 + 2 * jp + 1]);
    }
    for (int i = tid; i < MM * DD; i += 128) Mv[i] = Mv0[i];
    bfb[tid] = fb[tid]; bab[tid] = ab[tid]; beb[tid] = eb[tid]; badb[tid] = addb[tid];
    __syncthreads();

    for (int t = 0; t < TT; t++) {
        const int idx = b * TT + t;
        if (tid < MM) wbuf[tid] = g_w[idx * MM + tid];
        xbuf[128 + tid] = g_k[idx * DD + tid];
        const float yqv = g_yq[idx * DD + tid];
        __syncthreads();
        // read = w @ Mv
        float r0 = 0.f, r1 = 0.f;
#pragma unroll 5
        for (int m = 0; m < MM; m += 2) {
            r0 = fmaf(wbuf[m], Mv[m * DD + tid], r0);
            r1 = fmaf(wbuf[m + 1], Mv[(m + 1) * DD + tid], r1);
        }
        xbuf[tid] = r0 + r1;
        __syncthreads();
        // f = tanh([read,k] @ f_W.T + f_b)
        float a0 = bfb[tid], a1 = 0.f, a2 = 0.f, a3 = 0.f;
#pragma unroll 4
        for (int jp = 0; jp < 128; jp += 4) {
            float2 x0 = *(const float2*)&xbuf[2 * jp];
            float2 x1 = *(const float2*)&xbuf[2 * jp + 2];
            float2 x2 = *(const float2*)&xbuf[2 * jp + 4];
            float2 x3 = *(const float2*)&xbuf[2 * jp + 6];
            float2 w0 = __half22float2(fT2[jp * 128 + tid]);
            float2 w1 = __half22float2(fT2[(jp + 1) * 128 + tid]);
            float2 w2 = __half22float2(fT2[(jp + 2) * 128 + tid]);
            float2 w3 = __half22float2(fT2[(jp + 3) * 128 + tid]);
            a0 += x0.x * w0.x; a0 += x0.y * w0.y;
            a1 += x1.x * w1.x; a1 += x1.y * w1.y;
            a2 += x2.x * w2.x; a2 += x2.y * w2.y;
            a3 += x3.x * w3.x; a3 += x3.y * w3.y;
        }
        const float fv = tanhf((a0 + a1) + (a2 + a3));
        fbuf[tid] = fv;
        g_f[idx * DD + tid] = fv;
        __syncthreads();
        // y = yq + f @ a_Wf.T + a_b
        float y0 = bab[tid] + yqv, y1 = 0.f;
#pragma unroll 4
        for (int jp = 0; jp < 64; jp += 2) {
            float2 x0 = *(const float2*)&fbuf[2 * jp];
            float2 x1 = *(const float2*)&fbuf[2 * jp + 2];
            float2 w0 = __half22float2(aT2[jp * 128 + tid]);
            float2 w1 = __half22float2(aT2[(jp + 1) * 128 + tid]);
            y0 += x0.x * w0.x; y0 += x0.y * w0.y;
            y1 += x1.x * w1.x; y1 += x1.y * w1.y;
        }
        ybuf[tid] = y0 + y1;
        __syncthreads();
        // e = sigmoid(y @ e_W.T + e_b), a = tanh(y @ add_W.T + add_b)
        float e0 = beb[tid], e1 = 0.f, d0 = badb[tid], d1 = 0.f;
#pragma unroll 4
        for (int jp = 0; jp < 64; jp += 2) {
            float2 x0 = *(const float2*)&ybuf[2 * jp];
            float2 x1 = *(const float2*)&ybuf[2 * jp + 2];
            float2 we0 = __half22float2(eaT2[jp * 256 + tid]);
            float2 wa0 = __half22float2(eaT2[jp * 256 + 128 + tid]);
            float2 we1 = __half22float2(eaT2[(jp + 1) * 256 + tid]);
            float2 wa1 = __half22float2(eaT2[(jp + 1) * 256 + 128 + tid]);
            e0 += x0.x * we0.x; e0 += x0.y * we0.y;
            d0 += x0.x * wa0.x; d0 += x0.y * wa0.y;
            e1 += x1.x * we1.x; e1 += x1.y * we1.y;
            d1 += x1.x * wa1.x; d1 += x1.y * wa1.y;
        }
        const float ev = 1.f / (1.f + expf(-(e0 + e1)));
        const float av = tanhf(d0 + d1);
        // Mv update (thread owns column tid)
#pragma unroll 5
        for (int m = 0; m < MM; m++) {
            const float wm = wbuf[m];
            const int o = m * DD + tid;
            Mv[o] = Mv[o] * (1.f - wm * ev) + wm * av;
        }
        __syncthreads();
    }
}

// ---------------- Kernel D: gi = f_all @ Wih.T + (bih + bhh) -------------------
__global__ __launch_bounds__(256) void kD(const float* __restrict__ Wih,
                                          const float* __restrict__ bih,
                                          const float* __restrict__ bhh) {
    __shared__ float sA[64][68];
    __shared__ float sB[64][68];
    const int tid = threadIdx.x;
    const int row0 = blockIdx.x * 64;
    const int n0 = blockIdx.y * 64;
    const int tx = tid & 15, ty = tid >> 4;
    float acc[4][4];
#pragma unroll
    for (int i = 0; i < 4; i++)
#pragma unroll
        for (int j = 0; j < 4; j++) acc[i][j] = 0.f;

    for (int kk = 0; kk < 128; kk += 64) {
        __syncthreads();
#pragma unroll
        for (int l = 0; l < 4; l++) {
            const int li = tid + l * 256;  // float4 index, 0..1023
            const int m = li >> 4;
            const int kq = li & 15;
            float4 v = *(const float4*)&g_f[(size_t)(row0 + m) * DD + kk + kq * 4];
            sA[kq * 4 + 0][m] = v.x; sA[kq * 4 + 1][m] = v.y;
            sA[kq * 4 + 2][m] = v.z; sA[kq * 4 + 3][m] = v.w;
            float4 u = *(const float4*)&Wih[(size_t)(n0 + m) * DD + kk + kq * 4];
            sB[kq * 4 + 0][m] = u.x; sB[kq * 4 + 1][m] = u.y;
            sB[kq * 4 + 2][m] = u.z; sB[kq * 4 + 3][m] = u.w;
        }
        __syncthreads();
#pragma unroll 8
        for (int k = 0; k < 64; k++) {
            float4 a4 = *(const float4*)&sA[k][ty * 4];
            float4 b4 = *(const float4*)&sB[k][tx * 4];
            acc[0][0] += a4.x * b4.x; acc[0][1] += a4.x * b4.y;
            acc[0][2] += a4.x * b4.z; acc[0][3] += a4.x * b4.w;
            acc[1][0] += a4.y * b4.x; acc[1][1] += a4.y * b4.y;
            acc[1][2] += a4.y * b4.z; acc[1][3] += a4.y * b4.w;
            acc[2][0] += a4.z * b4.x; acc[2][1] += a4.z * b4.y;
            acc[2][2] += a4.z * b4.z; acc[2][3] += a4.z * b4.w;
            acc[3][0] += a4.w * b4.x; acc[3][1] += a4.w * b4.y;
            acc[3][2] += a4.w * b4.z; acc[3][3] += a4.w * b4.w;
        }
    }
#pragma unroll
    for (int i = 0; i < 4; i++) {
        const int rrow = row0 + ty * 4 + i;
#pragma unroll
        for (int j = 0; j < 4; j++) {
            const int n = n0 + tx * 4 + j;
            g_gi[(size_t)rrow * G4 + n] = acc[i][j] + bih[n] + bhh[n];
        }
    }
}

// ---------------- Kernel E: sequential LSTM with skip routing (1 block/batch) --
#define E_SMEM (64 * G4 * 4)
__global__ __launch_bounds__(128) void kE(const float* __restrict__ Whh,
                                          const float* __restrict__ pW,
                                          const float* __restrict__ pb,
                                          float* __restrict__ out) {
    extern __shared__ char sm2[];
    half2* whh2 = (half2*)sm2;  // [jp][512]
    __shared__ float hbuf[DD];
    __shared__ float red[4];
    const int tid = threadIdx.x;
    const int b = blockIdx.x;
    const int lane = tid & 31, warp = tid >> 5;

    for (int i = tid; i < 64 * G4; i += 128) {
        const int jp = i >> 9, g = i & 511;
        whh2[i] = __floats2half2_rn(Whh[g * DD + 2 * jp], Whh[g * DD + 2 * jp + 1]);
    }
    const float pw = pW[tid];
    const float pbv = pb[0];
    float h = 0.f, c = 0.f;
    __syncthreads();

    for (int t = 0; t < TT; t++) {
        const int idx = b * TT + t;
        float cin;
        if (g_match[idx]) {
            const int pv = g_prev[idx];
            hbuf[tid] = g_H[(size_t)(b * TT + pv) * DD + tid];
            cin = g_C[(size_t)(b * TT + pv) * DD + tid];
        } else {
            hbuf[tid] = h;
            cin = c;
        }
        __syncthreads();
        float gi_i = g_gi[(size_t)idx * G4 + tid];
        float gi_f = g_gi[(size_t)idx * G4 + 128 + tid];
        float gi_g = g_gi[(size_t)idx * G4 + 256 + tid];
        float gi_o = g_gi[(size_t)idx * G4 + 384 + tid];
#pragma unroll 4
        for (int jp = 0; jp < 64; jp++) {
            float2 h2 = *(const float2*)&hbuf[2 * jp];
            float2 wi = __half22float2(whh2[jp * G4 + tid]);
            float2 wf = __half22float2(whh2[jp * G4 + 128 + tid]);
            float2 wg = __half22float2(whh2[jp * G4 + 256 + tid]);
            float2 wo = __half22float2(whh2[jp * G4 + 384 + tid]);
            gi_i += h2.x * wi.x; gi_i += h2.y * wi.y;
            gi_f += h2.x * wf.x; gi_f += h2.y * wf.y;
            gi_g += h2.x * wg.x; gi_g += h2.y * wg.y;
            gi_o += h2.x * wo.x; gi_o += h2.y * wo.y;
        }
        const float ig = 1.f / (1.f + expf(-gi_i));
        const float fg = 1.f / (1.f + expf(-gi_f));
        const float gg = tanhf(gi_g);
        const float og = 1.f / (1.f + expf(-gi_o));
        c = fg * cin + ig * gg;
        h = og * tanhf(c);
        g_H[(size_t)idx * DD + tid] = h;
        g_C[(size_t)idx * DD + tid] = c;
        float pv_ = warp_sum(h * pw);
        if (lane == 0) red[warp] = pv_;
        __syncthreads();
        if (tid == 0)
            out[idx] = 1.f / (1.f + expf(-(red[0] + red[1] + red[2] + red[3] + pbv)));
    }
}

// ---------------- launch ----------------
extern "C" void kernel_launch(void* const* d_in, const int* in_sizes, int n_in,
                              void* d_out, int out_size) {
    const int* q = (const int*)d_in[0];
    const int* r = (const int*)d_in[1];
    const float* k_emb = (const float*)d_in[2];
    const float* Mk = (const float*)d_in[3];
    const float* Mv0 = (const float*)d_in[4];
    const float* fW = (const float*)d_in[5];
    const float* fb = (const float*)d_in[6];
    const float* aW = (const float*)d_in[7];
    const float* ab = (const float*)d_in[8];
    const float* eW = (const float*)d_in[9];
    const float* eb = (const float*)d_in[10];
    const float* addW = (const float*)d_in[11];
    const float* addb = (const float*)d_in[12];
    const float* Wih = (const float*)d_in[13];
    const float* Whh = (const float*)d_in[14];
    const float* bih = (const float*)d_in[15];
    const float* bhh = (const float*)d_in[16];
    const float* pW = (const float*)d_in[17];
    const float* pb = (const float*)d_in[18];
    float* out = (float*)d_out;

    cudaFuncSetAttribute(kC, cudaFuncAttributeMaxDynamicSharedMemorySize, C_SMEM);
    cudaFuncSetAttribute(kE, cudaFuncAttributeMaxDynamicSharedMemorySize, E_SMEM);

    kA<<<256, 256>>>(q, r, k_emb, Mk, aW);
    kB<<<RR / 8, 256>>>();
    kC<<<BSZ, 128, C_SMEM>>>(fW, fb, aW, ab, eW, eb, addW, addb, Mv0);
    kD<<<dim3(RR / 64, G4 / 64), 256>>>(Wih, bih, bhh);
    kE<<<BSZ, 128, E_SMEM>>>(Whh, pW, pb, out);
}

// round 4
// speedup vs baseline: 1.4751x; 1.4751x over previous
#include <cuda_runtime.h>
#include <cuda_fp16.h>

#define BSZ 32
#define TT 512
#define DD 128
#define MM 50
#define NUMC 4096
#define AWC (NUMC + DD)
#define G4 512
#define RR (BSZ * TT)

// ---------------- scratch (static device arrays; no allocation) ----------------
__device__ float g_k[RR * DD];
__device__ float g_yq[RR * DD];
__device__ float g_w[RR * MM];
__device__ unsigned long long g_pack[RR * 2];
__device__ int g_prev[RR];
__device__ int g_match[RR];
__device__ float g_f[RR * DD];
__device__ float g_gi[RR * G4];
__device__ float g_H[RR * DD];
__device__ float g_C[RR * DD];

__device__ __forceinline__ float warp_sum(float v) {
#pragma unroll
    for (int o = 16; o; o >>= 1) v += __shfl_xor_sync(0xffffffffu, v, o);
    return v;
}

__device__ __forceinline__ half2 as_h2(unsigned u) { return *reinterpret_cast<half2*>(&u); }

__device__ __forceinline__ float sigf(float x) { return 1.f / (1.f + __expf(-x)); }

__device__ __forceinline__ void dot4_acc(half2& av, const uint4& wv, const uint4& xv) {
    av = __hfma2(as_h2(wv.x), as_h2(xv.x), av);
    av = __hfma2(as_h2(wv.y), as_h2(xv.y), av);
    av = __hfma2(as_h2(wv.z), as_h2(xv.z), av);
    av = __hfma2(as_h2(wv.w), as_h2(xv.w), av);
}

// ---------------- Kernel A: gather + logits + softmax + quantize/pack ----------
__global__ __launch_bounds__(256) void kA(const int* __restrict__ q,
                                          const int* __restrict__ r,
                                          const float* __restrict__ k_emb,
                                          const float* __restrict__ Mk,
                                          const float* __restrict__ aW) {
    __shared__ float sMk[MM * DD];
    __shared__ float sk[DD];
    __shared__ float slog[MM];
    const int tid = threadIdx.x;
    for (int i = tid; i < MM * DD; i += 256) sMk[i] = Mk[i];
    const int base = blockIdx.x * 64;
    const int warp = tid >> 5, lane = tid & 31;

    for (int p = 0; p < 64; p++) {
        const int idx = base + p;
        __syncthreads();
        if (tid < DD) {
            const int qv = q[idx];
            const float kv = k_emb[qv * DD + tid];
            sk[tid] = kv;
            g_k[idx * DD + tid] = kv;
            g_yq[idx * DD + tid] = aW[tid * AWC + qv] * (float)r[idx];
        }
        __syncthreads();
        for (int m = warp; m < MM; m += 8) {
            float s = 0.f;
#pragma unroll
            for (int c = 0; c < 4; c++) s = fmaf(sk[c * 32 + lane], sMk[m * DD + c * 32 + lane], s);
            s = warp_sum(s);
            if (lane == 0) slog[m] = s;
        }
        __syncthreads();
        if (warp == 0) {
            float l0 = (lane < MM) ? slog[lane] : -1e30f;
            float l1 = (lane + 32 < MM) ? slog[lane + 32] : -1e30f;
            float mx = fmaxf(l0, l1);
#pragma unroll
            for (int o = 16; o; o >>= 1) mx = fmaxf(mx, __shfl_xor_sync(0xffffffffu, mx, o));
            float e0 = (lane < MM) ? expf(l0 - mx) : 0.f;
            float e1 = (lane + 32 < MM) ? expf(l1 - mx) : 0.f;
            float ssum = warp_sum(e0 + e1);
            float w0 = e0 / ssum, w1 = e1 / ssum;
            if (lane < MM) g_w[idx * MM + lane] = w0;
            if (lane + 32 < MM) g_w[idx * MM + lane + 32] = w1;
            const float ta = 0.075f;
            const float dba = (float)(0.088 - 0.075);
            const float dcb = (float)(1.0 - 0.088);
            float tw0 = fmaxf(fminf((w0 - ta) / dba, (1.0f - w0) / dcb), 0.f);
            float tw1 = fmaxf(fminf((w1 - ta) / dba, (1.0f - w1) / dcb), 0.f);
            int c0 = (lane < MM) ? (tw0 >= 0.6f ? 2 : (tw0 >= 0.1f ? 1 : 0)) : 0;
            int c1 = (lane + 32 < MM) ? (tw1 >= 0.6f ? 2 : (tw1 >= 0.1f ? 1 : 0)) : 0;
            unsigned b00 = __ballot_sync(0xffffffffu, c0 & 1);
            unsigned b01 = __ballot_sync(0xffffffffu, c0 >> 1);
            unsigned b10 = __ballot_sync(0xffffffffu, c1 & 1);
            unsigned b11 = __ballot_sync(0xffffffffu, c1 >> 1);
            if (lane == 0) {
                g_pack[idx * 2 + 0] = (unsigned long long)b00 | ((unsigned long long)b01 << 32);
                g_pack[idx * 2 + 1] = (unsigned long long)b10 | ((unsigned long long)b11 << 32);
            }
        }
    }
}

// ---------------- Kernel B: matched/prev via warp ballot backward scan ---------
__global__ __launch_bounds__(256) void kB() {
    const int gw = blockIdx.x * 8 + (threadIdx.x >> 5);
    const int lane = threadIdx.x & 31;
    const int b = gw / TT, i = gw % TT;
    const unsigned long long m0 = g_pack[gw * 2], m1 = g_pack[gw * 2 + 1];
    const unsigned long long* rp = &g_pack[(size_t)b * TT * 2];
    int prev = 0, matched = 0;
    for (int base = i - 1; base >= 0; base -= 32) {
        const int j = base - lane;
        const bool eq = (j >= 0) && (rp[j * 2] == m0) && (rp[j * 2 + 1] == m1);
        const unsigned msk = __ballot_sync(0xffffffffu, eq);
        if (msk) { matched = 1; prev = base - (__ffs(msk) - 1); break; }
    }
    if (lane == 0) { g_prev[gw] = prev; g_match[gw] = matched; }
}

// ---------------- Kernel C: memory-network scan, 2 batches per 128-thread block
// smem: fS 0..65536 | aS ..98304 | eS ..131072 | adS ..163840
//       xh4 ..164864 | fh4 ..165376 | yh4 ..165888 | wbuf ..166912
#define C_SMEM 166912
__global__ __launch_bounds__(128) void kC(const float* __restrict__ fW,
                                          const float* __restrict__ fb,
                                          const float* __restrict__ aW,
                                          const float* __restrict__ ab,
                                          const float* __restrict__ eW,
                                          const float* __restrict__ eb,
                                          const float* __restrict__ addW,
                                          const float* __restrict__ addb,
                                          const float* __restrict__ Mv0) {
    extern __shared__ char sm[];
    uint4* fS = (uint4*)sm;                 // [32*128] : 256-in x 128-out, half2x4
    uint4* aS = (uint4*)(sm + 65536);       // [16*128]
    uint4* eS = (uint4*)(sm + 98304);       // [16*128]
    uint4* adS = (uint4*)(sm + 131072);     // [16*128]
    uint4* xh4 = (uint4*)(sm + 163840);     // [2][32]
    uint4* fh4 = (uint4*)(sm + 164864);     // [2][16]
    uint4* yh4 = (uint4*)(sm + 165376);     // [2][16]
    float* wbuf = (float*)(sm + 165888);    // [2 parity][2 batch][64]
    half2* xh2 = (half2*)xh4;
    half2* fh2 = (half2*)fh4;
    half2* yh2 = (half2*)yh4;

    const int tid = threadIdx.x;
    const int b0 = blockIdx.x * 2;

    for (int i = tid; i < 128 * 128; i += 128) {
        const int jp = i >> 7, o = i & 127;
        ((half2*)fS)[(((jp >> 2) * 128 + o) << 2) + (jp & 3)] =
            __floats2half2_rn(fW[o * 256 + 2 * jp], fW[o * 256 + 2 * jp + 1]);
    }
    for (int i = tid; i < 64 * 128; i += 128) {
        const int jp = i >> 7, o = i & 127;
        const int d = (((jp >> 2) * 128 + o) << 2) + (jp & 3);
        ((half2*)aS)[d] =
            __floats2half2_rn(aW[o * AWC + NUMC + 2 * jp], aW[o * AWC + NUMC + 2 * jp + 1]);
        ((half2*)eS)[d] = __floats2half2_rn(eW[o * 128 + 2 * jp], eW[o * 128 + 2 * jp + 1]);
        ((half2*)adS)[d] = __floats2half2_rn(addW[o * 128 + 2 * jp], addW[o * 128 + 2 * jp + 1]);
    }
    const float bfv = fb[tid], bav = ab[tid], bev = eb[tid], badv = addb[tid];
    float Mva[MM], Mvb[MM];
#pragma unroll
    for (int m = 0; m < MM; m++) {
        const float v = Mv0[m * DD + tid];
        Mva[m] = v; Mvb[m] = v;
    }
    __syncthreads();

    const half2 z = __float2half2_rn(0.f);
    for (int t = 0; t < TT; t++) {
        const int idx0 = (b0)*TT + t, idx1 = idx0 + TT;
        const int par = (t & 1) << 7;
        if (tid < MM) {
            wbuf[par + tid] = g_w[idx0 * MM + tid];
            wbuf[par + 64 + tid] = g_w[idx1 * MM + tid];
        }
        {
            const float k0 = g_k[idx0 * DD + tid], k1 = g_k[idx1 * DD + tid];
            const float o0 = __shfl_xor_sync(0xffffffffu, k0, 1);
            const float o1 = __shfl_xor_sync(0xffffffffu, k1, 1);
            if (!(tid & 1)) {
                xh2[64 + (tid >> 1)] = __floats2half2_rn(k0, o0);
                xh2[128 + 64 + (tid >> 1)] = __floats2half2_rn(k1, o1);
            }
        }
        const float yq0 = g_yq[idx0 * DD + tid], yq1 = g_yq[idx1 * DD + tid];
        __syncthreads();  // 1

        // read = w @ Mv (registers)
        float ra0 = 0.f, ra1 = 0.f, rb0 = 0.f, rb1 = 0.f;
#pragma unroll
        for (int m = 0; m < MM; m += 2) {
            ra0 = fmaf(wbuf[par + m], Mva[m], ra0);
            ra1 = fmaf(wbuf[par + m + 1], Mva[m + 1], ra1);
            rb0 = fmaf(wbuf[par + 64 + m], Mvb[m], rb0);
            rb1 = fmaf(wbuf[par + 64 + m + 1], Mvb[m + 1], rb1);
        }
        {
            const float rA = ra0 + ra1, rB = rb0 + rb1;
            const float oA = __shfl_xor_sync(0xffffffffu, rA, 1);
            const float oB = __shfl_xor_sync(0xffffffffu, rB, 1);
            if (!(tid & 1)) {
                xh2[tid >> 1] = __floats2half2_rn(rA, oA);
                xh2[128 + (tid >> 1)] = __floats2half2_rn(rB, oB);
            }
        }
        __syncthreads();  // 2

        // f = tanh([read,k] @ f_W.T + f_b)
        half2 FA[8] = {z, z, z, z, z, z, z, z};
        half2 FB[8] = {z, z, z, z, z, z, z, z};
#pragma unroll
        for (int j = 0; j < 32; j++) {
            const uint4 wv = fS[j * 128 + tid];
            const uint4 x0 = xh4[j];
            const uint4 x1 = xh4[32 + j];
            const int p = (j & 1) << 2;
            FA[p + 0] = __hfma2(as_h2(wv.x), as_h2(x0.x), FA[p + 0]);
            FA[p + 1] = __hfma2(as_h2(wv.y), as_h2(x0.y), FA[p + 1]);
            FA[p + 2] = __hfma2(as_h2(wv.z), as_h2(x0.z), FA[p + 2]);
            FA[p + 3] = __hfma2(as_h2(wv.w), as_h2(x0.w), FA[p + 3]);
            FB[p + 0] = __hfma2(as_h2(wv.x), as_h2(x1.x), FB[p + 0]);
            FB[p + 1] = __hfma2(as_h2(wv.y), as_h2(x1.y), FB[p + 1]);
            FB[p + 2] = __hfma2(as_h2(wv.z), as_h2(x1.z), FB[p + 2]);
            FB[p + 3] = __hfma2(as_h2(wv.w), as_h2(x1.w), FB[p + 3]);
        }
        float sA = bfv, sB = bfv;
#pragma unroll
        for (int qq = 0; qq < 8; qq++) {
            const float2 e = __half22float2(FA[qq]);
            const float2 f2v = __half22float2(FB[qq]);
            sA += e.x + e.y;
            sB += f2v.x + f2v.y;
        }
        const float fv0 = tanhf(sA), fv1 = tanhf(sB);
        g_f[idx0 * DD + tid] = fv0;
        g_f[idx1 * DD + tid] = fv1;
        {
            const float o0 = __shfl_xor_sync(0xffffffffu, fv0, 1);
            const float o1 = __shfl_xor_sync(0xffffffffu, fv1, 1);
            if (!(tid & 1)) {
                fh2[tid >> 1] = __floats2half2_rn(fv0, o0);
                fh2[64 + (tid >> 1)] = __floats2half2_rn(fv1, o1);
            }
        }
        __syncthreads();  // 3

        // y = yq + f @ a_Wf.T + a_b
        half2 YA[4] = {z, z, z, z}, YB[4] = {z, z, z, z};
#pragma unroll
        for (int j = 0; j < 16; j++) {
            const uint4 wv = aS[j * 128 + tid];
            const uint4 x0 = fh4[j];
            const uint4 x1 = fh4[16 + j];
            dot4_acc(YA[j & 1 ? 1 : 0], wv, x0);
            dot4_acc(YA[j & 1 ? 3 : 2], wv, x0);
            dot4_acc(YB[j & 1 ? 1 : 0], wv, x1);
            dot4_acc(YB[j & 1 ? 3 : 2], wv, x1);
        }
        // NOTE: the duplicated dot4_acc above would double-count; use explicit form:
        // (re-zero and redo correctly)
        YA[0] = z; YA[1] = z; YA[2] = z; YA[3] = z;
        YB[0] = z; YB[1] = z; YB[2] = z; YB[3] = z;
#pragma unroll
        for (int j = 0; j < 16; j++) {
            const uint4 wv = aS[j * 128 + tid];
            const uint4 x0 = fh4[j];
            const uint4 x1 = fh4[16 + j];
            YA[0] = __hfma2(as_h2(wv.x), as_h2(x0.x), YA[0]);
            YA[1] = __hfma2(as_h2(wv.y), as_h2(x0.y), YA[1]);
            YA[2] = __hfma2(as_h2(wv.z), as_h2(x0.z), YA[2]);
            YA[3] = __hfma2(as_h2(wv.w), as_h2(x0.w), YA[3]);
            YB[0] = __hfma2(as_h2(wv.x), as_h2(x1.x), YB[0]);
            YB[1] = __hfma2(as_h2(wv.y), as_h2(x1.y), YB[1]);
            YB[2] = __hfma2(as_h2(wv.z), as_h2(x1.z), YB[2]);
            YB[3] = __hfma2(as_h2(wv.w), as_h2(x1.w), YB[3]);
        }
        float y0 = bav + yq0, y1 = bav + yq1;
#pragma unroll
        for (int qq = 0; qq < 4; qq++) {
            const float2 e = __half22float2(YA[qq]);
            const float2 f2v = __half22float2(YB[qq]);
            y0 += e.x + e.y;
            y1 += f2v.x + f2v.y;
        }
        {
            const float o0 = __shfl_xor_sync(0xffffffffu, y0, 1);
            const float o1 = __shfl_xor_sync(0xffffffffu, y1, 1);
            if (!(tid & 1)) {
                yh2[tid >> 1] = __floats2half2_rn(y0, o0);
                yh2[64 + (tid >> 1)] = __floats2half2_rn(y1, o1);
            }
        }
        __syncthreads();  // 4

        // e = sigmoid(y @ e_W.T + e_b), a = tanh(y @ add_W.T + add_b)
        half2 EA[4] = {z, z, z, z}, EB[4] = {z, z, z, z};
        half2 DA[4] = {z, z, z, z}, DB[4] = {z, z, z, z};
#pragma unroll
        for (int j = 0; j < 16; j++) {
            const uint4 we = eS[j * 128 + tid];
            const uint4 wa = adS[j * 128 + tid];
            const uint4 x0 = yh4[j];
            const uint4 x1 = yh4[16 + j];
            dot4_acc(EA[j & 3], we, x0);
            dot4_acc(DA[j & 3], wa, x0);
            dot4_acc(EB[j & 3], we, x1);
            dot4_acc(DB[j & 3], wa, x1);
        }
        float se0 = bev, se1 = bev, sd0 = badv, sd1 = badv;
#pragma unroll
        for (int qq = 0; qq < 4; qq++) {
            float2 e;
            e = __half22float2(EA[qq]); se0 += e.x + e.y;
            e = __half22float2(EB[qq]); se1 += e.x + e.y;
            e = __half22float2(DA[qq]); sd0 += e.x + e.y;
            e = __half22float2(DB[qq]); sd1 += e.x + e.y;
        }
        const float ev0 = sigf(se0), av0 = tanhf(sd0);
        const float ev1 = sigf(se1), av1 = tanhf(sd1);
#pragma unroll
        for (int m = 0; m < MM; m++) {
            const float wm0 = wbuf[par + m];
            const float wm1 = wbuf[par + 64 + m];
            Mva[m] = fmaf(wm0, fmaf(-ev0, Mva[m], av0), Mva[m]);
            Mvb[m] = fmaf(wm1, fmaf(-ev1, Mvb[m], av1), Mvb[m]);
        }
    }
}

// ---------------- Kernel D: gi = f_all @ Wih.T + (bih + bhh) -------------------
__global__ __launch_bounds__(256) void kD(const float* __restrict__ Wih,
                                          const float* __restrict__ bih,
                                          const float* __restrict__ bhh) {
    __shared__ float sA[64][68];
    __shared__ float sB[64][68];
    const int tid = threadIdx.x;
    const int row0 = blockIdx.x * 64;
    const int n0 = blockIdx.y * 64;
    const int tx = tid & 15, ty = tid >> 4;
    float acc[4][4];
#pragma unroll
    for (int i = 0; i < 4; i++)
#pragma unroll
        for (int j = 0; j < 4; j++) acc[i][j] = 0.f;

    for (int kk = 0; kk < 128; kk += 64) {
        __syncthreads();
#pragma unroll
        for (int l = 0; l < 4; l++) {
            const int li = tid + l * 256;
            const int m = li >> 4;
            const int kq = li & 15;
            float4 v = *(const float4*)&g_f[(size_t)(row0 + m) * DD + kk + kq * 4];
            sA[kq * 4 + 0][m] = v.x; sA[kq * 4 + 1][m] = v.y;
            sA[kq * 4 + 2][m] = v.z; sA[kq * 4 + 3][m] = v.w;
            float4 u = *(const float4*)&Wih[(size_t)(n0 + m) * DD + kk + kq * 4];
            sB[kq * 4 + 0][m] = u.x; sB[kq * 4 + 1][m] = u.y;
            sB[kq * 4 + 2][m] = u.z; sB[kq * 4 + 3][m] = u.w;
        }
        __syncthreads();
#pragma unroll 8
        for (int k = 0; k < 64; k++) {
            float4 a4 = *(const float4*)&sA[k][ty * 4];
            float4 b4 = *(const float4*)&sB[k][tx * 4];
            acc[0][0] += a4.x * b4.x; acc[0][1] += a4.x * b4.y;
            acc[0][2] += a4.x * b4.z; acc[0][3] += a4.x * b4.w;
            acc[1][0] += a4.y * b4.x; acc[1][1] += a4.y * b4.y;
            acc[1][2] += a4.y * b4.z; acc[1][3] += a4.y * b4.w;
            acc[2][0] += a4.z * b4.x; acc[2][1] += a4.z * b4.y;
            acc[2][2] += a4.z * b4.z; acc[2][3] += a4.z * b4.w;
            acc[3][0] += a4.w * b4.x; acc[3][1] += a4.w * b4.y;
            acc[3][2] += a4.w * b4.z; acc[3][3] += a4.w * b4.w;
        }
    }
#pragma unroll
    for (int i = 0; i < 4; i++) {
        const int rrow = row0 + ty * 4 + i;
#pragma unroll
        for (int j = 0; j < 4; j++) {
            const int n = n0 + tx * 4 + j;
            g_gi[(size_t)rrow * G4 + n] = acc[i][j] + bih[n] + bhh[n];
        }
    }
}

// ---------------- Kernel E: LSTM scan, 2 batches per 128-thread block ----------
#define E_SMEM (131072 + 512 + 64)
__global__ __launch_bounds__(128) void kE(const float* __restrict__ Whh,
                                          const float* __restrict__ pW,
                                          const float* __restrict__ pb,
                                          float* __restrict__ out) {
    extern __shared__ char sm2[];
    uint4* wS = (uint4*)sm2;                // [16*512]
    uint4* hh4 = (uint4*)(sm2 + 131072);    // [2][16]
    half2* hh2 = (half2*)hh4;
    float* red = (float*)(sm2 + 131584);    // [8]
    const int tid = threadIdx.x;
    const int b0 = blockIdx.x * 2;

    for (int i = tid; i < 64 * G4; i += 128) {
        const int jp = i >> 9, g = i & 511;
        ((half2*)wS)[(((jp >> 2) * G4 + g) << 2) + (jp & 3)] =
            __floats2half2_rn(Whh[g * DD + 2 * jp], Whh[g * DD + 2 * jp + 1]);
    }
    const float pw = pW[tid];
    const float pbv = pb[0];
    float h0 = 0.f, c0 = 0.f, h1 = 0.f, c1 = 0.f;
    __syncthreads();

    const half2 z = __float2half2_rn(0.f);
    for (int t = 0; t < TT; t++) {
        const int idx0 = b0 * TT + t, idx1 = idx0 + TT;
        float cin0, cin1;
        {
            float hv;
            if (g_match[idx0]) {
                const int pv = g_prev[idx0];
                hv = g_H[(size_t)(b0 * TT + pv) * DD + tid];
                cin0 = g_C[(size_t)(b0 * TT + pv) * DD + tid];
            } else { hv = h0; cin0 = c0; }
            const float o_ = __shfl_xor_sync(0xffffffffu, hv, 1);
            if (!(tid & 1)) hh2[tid >> 1] = __floats2half2_rn(hv, o_);
        }
        {
            float hv;
            if (g_match[idx1]) {
                const int pv = g_prev[idx1];
                hv = g_H[(size_t)((b0 + 1) * TT + pv) * DD + tid];
                cin1 = g_C[(size_t)((b0 + 1) * TT + pv) * DD + tid];
            } else { hv = h1; cin1 = c1; }
            const float o_ = __shfl_xor_sync(0xffffffffu, hv, 1);
            if (!(tid & 1)) hh2[64 + (tid >> 1)] = __floats2half2_rn(hv, o_);
        }
        __syncthreads();  // A

        half2 acc[16];
#pragma unroll
        for (int qq = 0; qq < 16; qq++) acc[qq] = z;
#pragma unroll
        for (int j = 0; j < 16; j++) {
            const uint4 x0 = hh4[j];
            const uint4 x1 = hh4[16 + j];
            const uint4 wi = wS[j * G4 + tid];
            const uint4 wf = wS[j * G4 + 128 + tid];
            const uint4 wg = wS[j * G4 + 256 + tid];
            const uint4 wo = wS[j * G4 + 384 + tid];
            const int p = j & 1;
            dot4_acc(acc[0 + p], wi, x0);
            dot4_acc(acc[2 + p], wi, x1);
            dot4_acc(acc[4 + p], wf, x0);
            dot4_acc(acc[6 + p], wf, x1);
            dot4_acc(acc[8 + p], wg, x0);
            dot4_acc(acc[10 + p], wg, x1);
            dot4_acc(acc[12 + p], wo, x0);
            dot4_acc(acc[14 + p], wo, x1);
        }
        float s[8];
#pragma unroll
        for (int qq = 0; qq < 8; qq++) {
            const float2 e = __half22float2(acc[2 * qq]);
            const float2 f2v = __half22float2(acc[2 * qq + 1]);
            s[qq] = e.x + e.y + f2v.x + f2v.y;
        }
        const float gi0 = g_gi[(size_t)idx0 * G4 + tid] + s[0];
        const float gf0 = g_gi[(size_t)idx0 * G4 + 128 + tid] + s[2];
        const float gg0 = g_gi[(size_t)idx0 * G4 + 256 + tid] + s[4];
        const float go0 = g_gi[(size_t)idx0 * G4 + 384 + tid] + s[6];
        const float gi1 = g_gi[(size_t)idx1 * G4 + tid] + s[1];
        const float gf1 = g_gi[(size_t)idx1 * G4 + 128 + tid] + s[3];
        const float gg1 = g_gi[(size_t)idx1 * G4 + 256 + tid] + s[5];
        const float go1 = g_gi[(size_t)idx1 * G4 + 384 + tid] + s[7];
        c0 = sigf(gf0) * cin0 + sigf(gi0) * tanhf(gg0);
        h0 = sigf(go0) * tanhf(c0);
        c1 = sigf(gf1) * cin1 + sigf(gi1) * tanhf(gg1);
        h1 = sigf(go1) * tanhf(c1);
        g_H[(size_t)idx0 * DD + tid] = h0;
        g_C[(size_t)idx0 * DD + tid] = c0;
        g_H[(size_t)idx1 * DD + tid] = h1;
        g_C[(size_t)idx1 * DD + tid] = c1;
        const float p0 = warp_sum(h0 * pw);
        const float p1 = warp_sum(h1 * pw);
        if ((tid & 31) == 0) {
            red[tid >> 5] = p0;
            red[4 + (tid >> 5)] = p1;
        }
        __syncthreads();  // B
        if (tid == 0) {
            out[idx0] = sigf(red[0] + red[1] + red[2] + red[3] + pbv);
            out[idx1] = sigf(red[4] + red[5] + red[6] + red[7] + pbv);
        }
    }
}

// ---------------- launch ----------------
extern "C" void kernel_launch(void* const* d_in, const int* in_sizes, int n_in,
                              void* d_out, int out_size) {
    const int* q = (const int*)d_in[0];
    const int* r = (const int*)d_in[1];
    const float* k_emb = (const float*)d_in[2];
    const float* Mk = (const float*)d_in[3];
    const float* Mv0 = (const float*)d_in[4];
    const float* fW = (const float*)d_in[5];
    const float* fb = (const float*)d_in[6];
    const float* aW = (const float*)d_in[7];
    const float* ab = (const float*)d_in[8];
    const float* eW = (const float*)d_in[9];
    const float* eb = (const float*)d_in[10];
    const float* addW = (const float*)d_in[11];
    const float* addb = (const float*)d_in[12];
    const float* Wih = (const float*)d_in[13];
    const float* Whh = (const float*)d_in[14];
    const float* bih = (const float*)d_in[15];
    const float* bhh = (const float*)d_in[16];
    const float* pW = (const float*)d_in[17];
    const float* pb = (const float*)d_in[18];
    float* out = (float*)d_out;

    cudaFuncSetAttribute(kC, cudaFuncAttributeMaxDynamicSharedMemorySize, C_SMEM);
    cudaFuncSetAttribute(kE, cudaFuncAttributeMaxDynamicSharedMemorySize, E_SMEM);

    kA<<<256, 256>>>(q, r, k_emb, Mk, aW);
    kB<<<RR / 8, 256>>>();
    kC<<<BSZ / 2, 128, C_SMEM>>>(fW, fb, aW, ab, eW, eb, addW, addb, Mv0);
    kD<<<dim3(RR / 64, G4 / 64), 256>>>(Wih, bih, bhh);
    kE<<<BSZ / 2, 128, E_SMEM>>>(Whh, pW, pb, out);
}